// round 10
// baseline (speedup 1.0000x reference)
#include <cuda_runtime.h>

// Loss_Antonymy: out = sum_i relu(1 + sign_i * tanh(||A1_i - S2_i||_2)),
// sign_i = -1 if labels[i]==2 else +1.
// N = 1048576, D = 64. Inputs: S2_out [N*64] f32, A1_out [N*64] f32, labels [N] int32.
// Output: 1 float.
//
// R10 (final): kernel is pinned at the B300 LTS chip cap (~6300 B/cyc ≈ 6.9 TB/s,
// path-independent), confirmed across 5 profiled variants. Configuration:
//  - half-warp per row, float4 loads, unroll x2 (MLP=4) [R3: +6% vs baseline]
//  - regs pinned <=32 via __launch_bounds__(256,8) -> 8 blocks/SM
//  - one balanced wave: SMs(152 on GB300) * 8 blocks
//  - fused last-block finalization, single launch, graph-replay-safe reset

#define D 64

__device__ float        g_partial = 0.0f;
__device__ unsigned int g_count   = 0u;

__global__ __launch_bounds__(256, 8)
void loss_antonymy_kernel(const float* __restrict__ S2,
                          const float* __restrict__ A1,
                          const int* __restrict__ labels,
                          float* __restrict__ out,
                          int nrows)
{
    const int lane  = threadIdx.x & 31;
    const int half  = lane >> 4;        // 0 or 1: which row within a pair
    const int sub   = lane & 15;        // 16 float4 = 64 floats of one row
    const int gwarp = (blockIdx.x * blockDim.x + threadIdx.x) >> 5;
    const int nwarp = (gridDim.x * blockDim.x) >> 5;
    const int nquads = nrows >> 2;      // 4 rows per warp iteration

    float acc = 0.0f;

    for (int quad = gwarp; quad < nquads; quad += nwarp) {
        const long long row0 = (long long)quad * 4 + half;
        const long long row1 = row0 + 2;

        const float4* a0 = reinterpret_cast<const float4*>(A1 + row0 * D);
        const float4* s0 = reinterpret_cast<const float4*>(S2 + row0 * D);
        const float4* a1 = reinterpret_cast<const float4*>(A1 + row1 * D);
        const float4* s1 = reinterpret_cast<const float4*>(S2 + row1 * D);

        // front-batch 4 independent 16B loads (MLP=4 per thread)
        float4 av0 = __ldg(&a0[sub]);
        float4 sv0 = __ldg(&s0[sub]);
        float4 av1 = __ldg(&a1[sub]);
        float4 sv1 = __ldg(&s1[sub]);

        float dx0 = av0.x - sv0.x, dy0 = av0.y - sv0.y;
        float dz0 = av0.z - sv0.z, dw0 = av0.w - sv0.w;
        float ss0 = dx0*dx0 + dy0*dy0 + dz0*dz0 + dw0*dw0;

        float dx1 = av1.x - sv1.x, dy1 = av1.y - sv1.y;
        float dz1 = av1.z - sv1.z, dw1 = av1.w - sv1.w;
        float ss1 = dx1*dx1 + dy1*dy1 + dz1*dz1 + dw1*dw1;

        // reduce each across the 16 lanes of this half-warp
        #pragma unroll
        for (int o = 8; o > 0; o >>= 1) {
            ss0 += __shfl_xor_sync(0xffffffffu, ss0, o);
            ss1 += __shfl_xor_sync(0xffffffffu, ss1, o);
        }

        if (sub == 0) {
            float sign0 = (labels[row0] == 2) ? -1.0f : 1.0f;
            float sign1 = (labels[row1] == 2) ? -1.0f : 1.0f;
            acc += fmaxf(0.0f, fmaf(sign0, tanhf(sqrtf(ss0)), 1.0f));
            acc += fmaxf(0.0f, fmaf(sign1, tanhf(sqrtf(ss1)), 1.0f));
        }
    }

    // block reduction: intra-warp, then across warps via shared
    #pragma unroll
    for (int o = 16; o > 0; o >>= 1)
        acc += __shfl_xor_sync(0xffffffffu, acc, o);

    __shared__ float wsum[8];   // 256 threads -> 8 warps
    const int wid = threadIdx.x >> 5;
    if (lane == 0) wsum[wid] = acc;
    __syncthreads();

    if (wid == 0) {
        float v = (lane < (blockDim.x >> 5)) ? wsum[lane] : 0.0f;
        #pragma unroll
        for (int o = 4; o > 0; o >>= 1)
            v += __shfl_xor_sync(0xffffffffu, v, o);

        if (lane == 0) {
            // accumulate into device-global partial; last block finalizes
            atomicAdd(&g_partial, v);
            __threadfence();
            unsigned int ticket = atomicAdd(&g_count, 1u);
            if (ticket == gridDim.x - 1u) {
                // all blocks' adds are globally visible (each fenced before its
                // ticket). Read-and-reset so the next graph replay starts clean.
                float total = atomicExch(&g_partial, 0.0f);
                out[0] = total;
                atomicExch(&g_count, 0u);
            }
        }
    }
}

extern "C" void kernel_launch(void* const* d_in, const int* in_sizes, int n_in,
                              void* d_out, int out_size)
{
    const float* S2     = (const float*)d_in[0];
    const float* A1     = (const float*)d_in[1];
    const int*   labels = (const int*)d_in[2];
    float*       out    = (float*)d_out;

    const int nrows = in_sizes[2];   // labels element count = N

    // One perfectly balanced wave at 8 blocks/SM on the real SM count
    // (GB300=152, B300-SXM=148). Attribute query is capture-safe.
    static int sms = 0;
    if (sms == 0) {
        cudaDeviceGetAttribute(&sms, cudaDevAttrMultiProcessorCount, 0);
        if (sms <= 0) sms = 148;
    }
    const int blocks = sms * 8;

    loss_antonymy_kernel<<<blocks, 256>>>(S2, A1, labels, out, nrows);
}

// round 11
// speedup vs baseline: 1.0287x; 1.0287x over previous
#include <cuda_runtime.h>

// Loss_Antonymy: out = sum_i relu(1 + sign_i * tanh(||A1_i - S2_i||_2)),
// sign_i = -1 if labels[i]==2 else +1.
// N = 1048576, D = 64. Inputs: S2_out [N*64] f32, A1_out [N*64] f32, labels [N] int32.
// Output: 1 float.
//
// R11 (final): measured-best configuration. This kernel is pinned at the B300
// LTS chip cap (~6300 B/cyc ≈ 6.9 TB/s, path-independent); confirmed across 6
// profiled variants (MLP 2/4/8, cache policy, wave shape, epilogue fusion all
// tested). Config:
//  - half-warp per row, float4 __ldg loads, unroll x2 (MLP=4/thread)
//  - separate 1-thread zero kernel (fused last-block epilogue measured SLOWER:
//    per-block __threadfence L1D-flush + same-address atomic tail > launch cost)
//  - regs pinned <=32 via __launch_bounds__(256,8) -> 8 blocks/SM
//  - one balanced wave: SMs(152 on GB300) * 8 blocks

#define D 64

__global__ void zero_out_kernel(float* out) {
    out[0] = 0.0f;
}

__global__ __launch_bounds__(256, 8)
void loss_antonymy_kernel(const float* __restrict__ S2,
                          const float* __restrict__ A1,
                          const int* __restrict__ labels,
                          float* __restrict__ out,
                          int nrows)
{
    const int lane  = threadIdx.x & 31;
    const int half  = lane >> 4;        // 0 or 1: which row within a pair
    const int sub   = lane & 15;        // 16 float4 = 64 floats of one row
    const int gwarp = (blockIdx.x * blockDim.x + threadIdx.x) >> 5;
    const int nwarp = (gridDim.x * blockDim.x) >> 5;
    const int nquads = nrows >> 2;      // 4 rows per warp iteration

    float acc = 0.0f;

    for (int quad = gwarp; quad < nquads; quad += nwarp) {
        const long long row0 = (long long)quad * 4 + half;
        const long long row1 = row0 + 2;

        const float4* a0 = reinterpret_cast<const float4*>(A1 + row0 * D);
        const float4* s0 = reinterpret_cast<const float4*>(S2 + row0 * D);
        const float4* a1 = reinterpret_cast<const float4*>(A1 + row1 * D);
        const float4* s1 = reinterpret_cast<const float4*>(S2 + row1 * D);

        // front-batch 4 independent 16B loads (MLP=4 per thread)
        float4 av0 = __ldg(&a0[sub]);
        float4 sv0 = __ldg(&s0[sub]);
        float4 av1 = __ldg(&a1[sub]);
        float4 sv1 = __ldg(&s1[sub]);

        float dx0 = av0.x - sv0.x, dy0 = av0.y - sv0.y;
        float dz0 = av0.z - sv0.z, dw0 = av0.w - sv0.w;
        float ss0 = dx0*dx0 + dy0*dy0 + dz0*dz0 + dw0*dw0;

        float dx1 = av1.x - sv1.x, dy1 = av1.y - sv1.y;
        float dz1 = av1.z - sv1.z, dw1 = av1.w - sv1.w;
        float ss1 = dx1*dx1 + dy1*dy1 + dz1*dz1 + dw1*dw1;

        // reduce each across the 16 lanes of this half-warp
        #pragma unroll
        for (int o = 8; o > 0; o >>= 1) {
            ss0 += __shfl_xor_sync(0xffffffffu, ss0, o);
            ss1 += __shfl_xor_sync(0xffffffffu, ss1, o);
        }

        if (sub == 0) {
            float sign0 = (labels[row0] == 2) ? -1.0f : 1.0f;
            float sign1 = (labels[row1] == 2) ? -1.0f : 1.0f;
            acc += fmaxf(0.0f, fmaf(sign0, tanhf(sqrtf(ss0)), 1.0f));
            acc += fmaxf(0.0f, fmaf(sign1, tanhf(sqrtf(ss1)), 1.0f));
        }
    }

    // block reduction: intra-warp, then across warps via shared, one atomic per block
    #pragma unroll
    for (int o = 16; o > 0; o >>= 1)
        acc += __shfl_xor_sync(0xffffffffu, acc, o);

    __shared__ float wsum[8];   // 256 threads -> 8 warps
    const int wid = threadIdx.x >> 5;
    if (lane == 0) wsum[wid] = acc;
    __syncthreads();

    if (wid == 0) {
        float v = (lane < (blockDim.x >> 5)) ? wsum[lane] : 0.0f;
        #pragma unroll
        for (int o = 4; o > 0; o >>= 1)
            v += __shfl_xor_sync(0xffffffffu, v, o);
        if (lane == 0)
            atomicAdd(out, v);
    }
}

extern "C" void kernel_launch(void* const* d_in, const int* in_sizes, int n_in,
                              void* d_out, int out_size)
{
    const float* S2     = (const float*)d_in[0];
    const float* A1     = (const float*)d_in[1];
    const int*   labels = (const int*)d_in[2];
    float*       out    = (float*)d_out;

    const int nrows = in_sizes[2];   // labels element count = N

    zero_out_kernel<<<1, 1>>>(out);

    // One perfectly balanced wave at 8 blocks/SM on the real SM count
    // (GB300=152, B300-SXM=148). Attribute query is capture-safe.
    static int sms = 0;
    if (sms == 0) {
        cudaDeviceGetAttribute(&sms, cudaDevAttrMultiProcessorCount, 0);
        if (sms <= 0) sms = 148;
    }
    const int blocks = sms * 8;

    loss_antonymy_kernel<<<blocks, 256>>>(S2, A1, labels, out, nrows);
}

// round 12
// speedup vs baseline: 1.0332x; 1.0044x over previous
#include <cuda_runtime.h>

// Loss_Antonymy: out = sum_i relu(1 + sign_i * tanh(||A1_i - S2_i||_2)),
// sign_i = -1 if labels[i]==2 else +1.
// N = 1048576, D = 64. Inputs: S2_out [N*64] f32, A1_out [N*64] f32, labels [N] int32.
// Output: 1 float.
//
// R12: R11 + two tail/latency residual fixes:
//  - grid = 1024 blocks -> 8192 warps -> exactly 32 quads/warp (zero remainder,
//    clean drain; all blocks co-resident, DRAM pacing unaffected per R5)
//  - labels loads hoisted into the front load batch (all lanes, broadcast) so
//    the per-iteration MLP=1 scalar load overlaps the float4 stream instead of
//    serializing after the shuffle chain.

#define D 64

__global__ void zero_out_kernel(float* out) {
    out[0] = 0.0f;
}

__global__ __launch_bounds__(256, 8)
void loss_antonymy_kernel(const float* __restrict__ S2,
                          const float* __restrict__ A1,
                          const int* __restrict__ labels,
                          float* __restrict__ out,
                          int nrows)
{
    const int lane  = threadIdx.x & 31;
    const int half  = lane >> 4;        // 0 or 1: which row within a pair
    const int sub   = lane & 15;        // 16 float4 = 64 floats of one row
    const int gwarp = (blockIdx.x * blockDim.x + threadIdx.x) >> 5;
    const int nwarp = (gridDim.x * blockDim.x) >> 5;
    const int nquads = nrows >> 2;      // 4 rows per warp iteration

    float acc = 0.0f;

    for (int quad = gwarp; quad < nquads; quad += nwarp) {
        const long long row0 = (long long)quad * 4 + half;
        const long long row1 = row0 + 2;

        const float4* a0 = reinterpret_cast<const float4*>(A1 + row0 * D);
        const float4* s0 = reinterpret_cast<const float4*>(S2 + row0 * D);
        const float4* a1 = reinterpret_cast<const float4*>(A1 + row1 * D);
        const float4* s1 = reinterpret_cast<const float4*>(S2 + row1 * D);

        // front-batch all loads: 4 independent 16B vector loads + 2 broadcast
        // label words (overlap the scalar loads with the stream instead of
        // serializing them after the shuffle chain)
        float4 av0 = __ldg(&a0[sub]);
        float4 sv0 = __ldg(&s0[sub]);
        float4 av1 = __ldg(&a1[sub]);
        float4 sv1 = __ldg(&s1[sub]);
        int    lb0 = __ldg(&labels[row0]);
        int    lb1 = __ldg(&labels[row1]);

        float dx0 = av0.x - sv0.x, dy0 = av0.y - sv0.y;
        float dz0 = av0.z - sv0.z, dw0 = av0.w - sv0.w;
        float ss0 = dx0*dx0 + dy0*dy0 + dz0*dz0 + dw0*dw0;

        float dx1 = av1.x - sv1.x, dy1 = av1.y - sv1.y;
        float dz1 = av1.z - sv1.z, dw1 = av1.w - sv1.w;
        float ss1 = dx1*dx1 + dy1*dy1 + dz1*dz1 + dw1*dw1;

        // reduce each across the 16 lanes of this half-warp
        #pragma unroll
        for (int o = 8; o > 0; o >>= 1) {
            ss0 += __shfl_xor_sync(0xffffffffu, ss0, o);
            ss1 += __shfl_xor_sync(0xffffffffu, ss1, o);
        }

        if (sub == 0) {
            float sign0 = (lb0 == 2) ? -1.0f : 1.0f;
            float sign1 = (lb1 == 2) ? -1.0f : 1.0f;
            acc += fmaxf(0.0f, fmaf(sign0, tanhf(sqrtf(ss0)), 1.0f));
            acc += fmaxf(0.0f, fmaf(sign1, tanhf(sqrtf(ss1)), 1.0f));
        }
    }

    // block reduction: intra-warp, then across warps via shared, one atomic per block
    #pragma unroll
    for (int o = 16; o > 0; o >>= 1)
        acc += __shfl_xor_sync(0xffffffffu, acc, o);

    __shared__ float wsum[8];   // 256 threads -> 8 warps
    const int wid = threadIdx.x >> 5;
    if (lane == 0) wsum[wid] = acc;
    __syncthreads();

    if (wid == 0) {
        float v = (lane < (blockDim.x >> 5)) ? wsum[lane] : 0.0f;
        #pragma unroll
        for (int o = 4; o > 0; o >>= 1)
            v += __shfl_xor_sync(0xffffffffu, v, o);
        if (lane == 0)
            atomicAdd(out, v);
    }
}

extern "C" void kernel_launch(void* const* d_in, const int* in_sizes, int n_in,
                              void* d_out, int out_size)
{
    const float* S2     = (const float*)d_in[0];
    const float* A1     = (const float*)d_in[1];
    const int*   labels = (const int*)d_in[2];
    float*       out    = (float*)d_out;

    const int nrows = in_sizes[2];   // labels element count = N

    zero_out_kernel<<<1, 1>>>(out);

    // 1024 blocks = 8192 warps: 262144 quads / 8192 = exactly 32 iterations
    // per warp (zero remainder). All blocks co-resident (capacity 8/SM * 152).
    const int blocks = 1024;
    loss_antonymy_kernel<<<blocks, 256>>>(S2, A1, labels, out, nrows);
}